// round 5
// baseline (speedup 1.0000x reference)
#include <cuda_runtime.h>
#include <cstdint>

// Problem constants
#define NN    16384
#define KK    25
#define DD    256
#define OUTD  256
#define NTOT  100000
#define BAG   8
#define KDIM  (4 * DD)   // 1024

// K-dimension layout of g_X / g_M is pair-permuted within each 8-float block:
//   [k0,k4,k1,k5,k2,k6,k3,k7]
// so a tf32 mma fragment pair (k, k+4) is one LDS.64. Applied to both
// operands, so dot products are unchanged.

__device__ float g_M[OUTD * KDIM];          // fused weights, TF32, permuted K
__device__ float g_X[(size_t)NN * KDIM];    // features, TF32, permuted K (64 MB)

__device__ __forceinline__ float to_tf32(float x) {
    uint32_t r;
    asm("cvt.rna.tf32.f32 %0, %1;" : "=r"(r) : "f"(x));
    return __uint_as_float(r);
}

__device__ __forceinline__ void cp_async16(void* smem, const void* gmem) {
    uint32_t s = (uint32_t)__cvta_generic_to_shared(smem);
    asm volatile("cp.async.cg.shared.global [%0], [%1], 16;" :: "r"(s), "l"(gmem));
}

// ---------------------------------------------------------------------------
// K1 (merged): blocks [0,512) fuse weights, blocks [512, 512+16384) gather.
// Fuse is latency-bound with ~0 DRAM use; gather is DRAM-bound at ~72%.
// Running them concurrently hides fuse entirely under gather.
// ---------------------------------------------------------------------------
#define FUSE_BLOCKS 512

__global__ void __launch_bounds__(256) gather_fuse_kernel(
    const int*   __restrict__ nodes,
    const int*   __restrict__ neigh_idx,
    const float* __restrict__ table_self,
    const float* __restrict__ tables_to,
    const float* __restrict__ W_self,
    const float* __restrict__ W_rel,
    const float* __restrict__ W_comp)
{
    __shared__ float smem_u[2 * DD];           // fuse: float2[256]; gather: idx

    if (blockIdx.x < FUSE_BLOCKS) {
        // ---- fuse path: M_c = W_comp[:, c*256:+256] @ (W_rel[c] | W_self) ----
        const int c  = blockIdx.x >> 7;        // 0..3
        const int o0 = (blockIdx.x & 127) * 2; // 2 output rows
        float2* s_w = reinterpret_cast<float2*>(smem_u);
        {
            int j = threadIdx.x;
            s_w[j] = make_float2(W_comp[(size_t)o0 * KDIM + c * DD + j],
                                 W_comp[(size_t)(o0 + 1) * KDIM + c * DD + j]);
        }
        __syncthreads();

        const float* Wsrc = (c < 3) ? (W_rel + (size_t)c * OUTD * DD) : W_self;
        const int d = threadIdx.x;

        float acc0 = 0.f, acc1 = 0.f;
#pragma unroll 8
        for (int j = 0; j < DD; ++j) {
            float v = __ldg(Wsrc + (size_t)j * DD + d);
            float2 w = s_w[j];
            acc0 += w.x * v;
            acc1 += w.y * v;
        }
        const int pd = (d & ~7) | ((d & 3) << 1) | ((d >> 2) & 1);
        g_M[(size_t)o0 * KDIM + c * DD + pd]       = to_tf32(acc0);
        g_M[(size_t)(o0 + 1) * KDIM + c * DD + pd] = to_tf32(acc1);
        return;
    }

    // ---- gather path ----
    const int b   = blockIdx.x - FUSE_BLOCKS;
    const int c   = b >> 12;                   // relation 0..3 (slowest)
    const int bx  = b & 4095;
    const int sub = threadIdx.x >> 6;
    const int d4  = threadIdx.x & 63;
    const int n   = bx * 4 + sub;

    if (c == 3) {
        int i = __ldg(nodes + n);
        float4 v = reinterpret_cast<const float4*>(table_self + (size_t)i * DD)[d4];
        float* dst = g_X + (size_t)n * KDIM + 3 * DD + ((d4 >> 1) << 3) + (d4 & 1);
        dst[0] = to_tf32(v.x); dst[2] = to_tf32(v.y);
        dst[4] = to_tf32(v.z); dst[6] = to_tf32(v.w);
        return;
    }

    int (*s_idx)[KK] = reinterpret_cast<int (*)[KK]>(smem_u);
    if (threadIdx.x < 4 * KK) {
        int nn = bx * 4 + threadIdx.x / KK;
        int kk = threadIdx.x % KK;
        s_idx[threadIdx.x / KK][kk] = neigh_idx[((size_t)c * NN + nn) * KK + kk];
    }
    __syncthreads();

    const float* tbl = tables_to + (size_t)c * NTOT * DD;
    float4 acc = make_float4(0.f, 0.f, 0.f, 0.f);
#pragma unroll
    for (int k = 0; k < KK; ++k) {
        int i = s_idx[sub][k];
        float4 v = reinterpret_cast<const float4*>(tbl + (size_t)i * DD)[d4];
        acc.x += v.x; acc.y += v.y; acc.z += v.z; acc.w += v.w;
    }
    const float s = 1.f / (float)KK;
    float* dst = g_X + (size_t)n * KDIM + (size_t)c * DD + ((d4 >> 1) << 3) + (d4 & 1);
    dst[0] = to_tf32(acc.x * s); dst[2] = to_tf32(acc.y * s);
    dst[4] = to_tf32(acc.z * s); dst[6] = to_tf32(acc.w * s);
}

// ---------------------------------------------------------------------------
// K2: H = relu(X @ M^T); out = bag-mean(H, 8)
// TF32 mma m16n8k8. CTA 128x128, BK=32, 3-stage cp.async, XOR-swizzled smem,
// LDS.64 fragment loads via the pair-permuted gmem layout.
// ---------------------------------------------------------------------------
#define BM 128
#define BN 128
#define BK 32
#define NKC (KDIM / BK)                 // 32
#define STAGE_F (BM * BK + BN * BK)     // 8192 floats per stage
#define GEMM_SMEM_BYTES (3 * STAGE_F * 4)   // 98304 B

__global__ void __launch_bounds__(256, 2) gemm_relu_bag_kernel(float* __restrict__ out)
{
    extern __shared__ float smem[];

    const int tid  = threadIdx.x;
    const int lane = tid & 31;
    const int wid  = tid >> 5;
    const int wm   = wid & 3;
    const int wn   = wid >> 2;
    const int g    = lane >> 2;
    const int t    = lane & 3;

    const float* Abase = g_X + (size_t)blockIdx.x * BM * KDIM;
    const float* Bbase = g_M + (size_t)blockIdx.y * BN * KDIM;

    float acc[2][8][4];
#pragma unroll
    for (int i = 0; i < 2; ++i)
#pragma unroll
        for (int j = 0; j < 8; ++j)
#pragma unroll
            for (int r = 0; r < 4; ++r) acc[i][j][r] = 0.f;

#define STAGE_FILL(slot, ko)                                                   \
    {                                                                          \
        float* sA_ = smem + (slot) * STAGE_F;                                  \
        float* sB_ = sA_ + BM * BK;                                            \
        _Pragma("unroll")                                                      \
        for (int i_ = 0; i_ < 4; ++i_) {                                       \
            int f4_ = tid + i_ * 256;                                          \
            int r_  = f4_ >> 3;                                                \
            int c_  = f4_ & 7;                                                 \
            int cs_ = c_ ^ (r_ & 7);                                           \
            cp_async16(sA_ + r_ * BK + cs_ * 4,                                \
                       Abase + (size_t)r_ * KDIM + (ko) + c_ * 4);             \
            cp_async16(sB_ + r_ * BK + cs_ * 4,                                \
                       Bbase + (size_t)r_ * KDIM + (ko) + c_ * 4);             \
        }                                                                      \
        asm volatile("cp.async.commit_group;");                                \
    }

    STAGE_FILL(0, 0)
    STAGE_FILL(1, BK)

    for (int kc = 0; kc < NKC; ++kc) {
        if (kc + 1 < NKC) asm volatile("cp.async.wait_group 1;");
        else              asm volatile("cp.async.wait_group 0;");
        __syncthreads();

        if (kc + 2 < NKC) STAGE_FILL((kc + 2) % 3, (kc + 2) * BK)

        const float* As = smem + (kc % 3) * STAGE_F;
        const float* Bs = As + BM * BK;

#pragma unroll
        for (int kk = 0; kk < BK / 8; ++kk) {
            const int cidx = (((kk * 2 + (t >> 1)) ^ g) << 2) + ((t & 1) << 1);

            float2 a0[2], a1[2];
#pragma unroll
            for (int mi = 0; mi < 2; ++mi) {
                int r0 = wm * 32 + mi * 16 + g;
                a0[mi] = *reinterpret_cast<const float2*>(As + r0 * BK + cidx);
                a1[mi] = *reinterpret_cast<const float2*>(As + (r0 + 8) * BK + cidx);
            }
#pragma unroll
            for (int nj = 0; nj < 8; ++nj) {
                int cn = wn * 64 + nj * 8 + g;
                float2 b = *reinterpret_cast<const float2*>(Bs + cn * BK + cidx);
                uint32_t ub0 = __float_as_uint(b.x);
                uint32_t ub1 = __float_as_uint(b.y);
#pragma unroll
                for (int mi = 0; mi < 2; ++mi) {
                    asm volatile(
                        "mma.sync.aligned.m16n8k8.row.col.f32.tf32.tf32.f32 "
                        "{%0,%1,%2,%3}, {%4,%5,%6,%7}, {%8,%9}, {%0,%1,%2,%3};"
                        : "+f"(acc[mi][nj][0]), "+f"(acc[mi][nj][1]),
                          "+f"(acc[mi][nj][2]), "+f"(acc[mi][nj][3])
                        : "r"(__float_as_uint(a0[mi].x)),
                          "r"(__float_as_uint(a1[mi].x)),
                          "r"(__float_as_uint(a0[mi].y)),
                          "r"(__float_as_uint(a1[mi].y)),
                          "r"(ub0), "r"(ub1));
                }
            }
        }
    }
#undef STAGE_FILL

    // ---- epilogue: relu -> smem [128][128] -> bag-mean(8) -> out ----
    float* Cs = smem;
#pragma unroll
    for (int mi = 0; mi < 2; ++mi) {
#pragma unroll
        for (int nj = 0; nj < 8; ++nj) {
            int r0 = wm * 32 + mi * 16 + g;
            int c0 = wn * 64 + nj * 8 + 2 * t;
            Cs[r0 * BN + c0]           = fmaxf(acc[mi][nj][0], 0.f);
            Cs[r0 * BN + c0 + 1]       = fmaxf(acc[mi][nj][1], 0.f);
            Cs[(r0 + 8) * BN + c0]     = fmaxf(acc[mi][nj][2], 0.f);
            Cs[(r0 + 8) * BN + c0 + 1] = fmaxf(acc[mi][nj][3], 0.f);
        }
    }
    __syncthreads();

    const int col = tid & 127;
    const int h   = tid >> 7;
#pragma unroll
    for (int gg = h; gg < BM / BAG; gg += 2) {
        float s = 0.f;
#pragma unroll
        for (int r = 0; r < BAG; ++r) s += Cs[(gg * BAG + r) * BN + col];
        out[(size_t)(blockIdx.x * (BM / BAG) + gg) * OUTD + blockIdx.y * BN + col]
            = s * (1.f / BAG);
    }
}

// ---------------------------------------------------------------------------
extern "C" void kernel_launch(void* const* d_in, const int* in_sizes, int n_in,
                              void* d_out, int out_size)
{
    (void)in_sizes; (void)n_in; (void)out_size;
    const int*   nodes      = (const int*)  d_in[0];
    const int*   neigh_idx  = (const int*)  d_in[1];
    const float* table_self = (const float*)d_in[2];
    const float* tables_to  = (const float*)d_in[3];
    const float* W_self     = (const float*)d_in[4];
    const float* W_rel      = (const float*)d_in[5];
    const float* W_comp     = (const float*)d_in[6];
    float*       out        = (float*)d_out;

    cudaFuncSetAttribute(gemm_relu_bag_kernel,
                         cudaFuncAttributeMaxDynamicSharedMemorySize,
                         GEMM_SMEM_BYTES);

    gather_fuse_kernel<<<FUSE_BLOCKS + NN, 256>>>(
        nodes, neigh_idx, table_self, tables_to, W_self, W_rel, W_comp);
    gemm_relu_bag_kernel<<<dim3(NN / BM, OUTD / BN), 256, GEMM_SMEM_BYTES>>>(out);
}

// round 8
// speedup vs baseline: 1.2776x; 1.2776x over previous
#include <cuda_runtime.h>
#include <cstdint>

// Problem constants
#define NN    16384
#define KK    25
#define DD    256
#define OUTD  256
#define NTOT  100000
#define BAG   8
#define KDIM  1024

// K-dim layout of g_X / g_M is quad-permuted within each 16-float block:
//   pos(k) = (k & ~15) + 4*(k & 3) + ((k >> 2) & 3)
// so one LDS.128 at offset t*16 yields k = {t, t+4, t+8, t+12}: both tf32
// mma k8-slices of a 16-K block in a single load. Applied to BOTH operands,
// dot products are unchanged.

__device__ float g_M[OUTD * KDIM];          // fused weights, tf32, permuted K
__device__ float g_X[(size_t)NN * KDIM];    // features, tf32, permuted K (64 MB)

__device__ __forceinline__ float to_tf32(float x) {
    uint32_t r;
    asm("cvt.rna.tf32.f32 %0, %1;" : "=r"(r) : "f"(x));
    return __uint_as_float(r);
}
__device__ __forceinline__ void cp_async16(void* smem, const void* gmem) {
    uint32_t s = (uint32_t)__cvta_generic_to_shared(smem);
    asm volatile("cp.async.cg.shared.global [%0], [%1], 16;" :: "r"(s), "l"(gmem));
}

// ---------------------------------------------------------------------------
// K1: fuse weights.  M_c = W_comp[:, c*256:(c+1)*256] @ (W_rel[c] | W_self)
// 2 o-rows per block -> 512 blocks (full chip).
// ---------------------------------------------------------------------------
__global__ void __launch_bounds__(256) fuse_weights_kernel(
    const float* __restrict__ W_self,
    const float* __restrict__ W_rel,
    const float* __restrict__ W_comp)
{
    const int c  = blockIdx.x >> 7;
    const int o0 = (blockIdx.x & 127) * 2;

    __shared__ float2 s_w[DD];
    {
        int j = threadIdx.x;
        s_w[j] = make_float2(W_comp[(size_t)o0 * KDIM + c * DD + j],
                             W_comp[(size_t)(o0 + 1) * KDIM + c * DD + j]);
    }
    __syncthreads();

    const float* Wsrc = (c < 3) ? (W_rel + (size_t)c * OUTD * DD) : W_self;
    const int d = threadIdx.x;

    float acc0 = 0.f, acc1 = 0.f;
#pragma unroll 8
    for (int j = 0; j < DD; ++j) {
        float v = __ldg(Wsrc + (size_t)j * DD + d);
        float2 w = s_w[j];
        acc0 += w.x * v;
        acc1 += w.y * v;
    }
    const int pd = (d & ~15) + ((d & 3) << 2) + ((d >> 2) & 3);   // quad-permute
    g_M[(size_t)o0 * KDIM + c * DD + pd]       = to_tf32(acc0);
    g_M[(size_t)(o0 + 1) * KDIM + c * DD + pd] = to_tf32(acc1);
}

// ---------------------------------------------------------------------------
// K2: gather + mean -> g_X (tf32, quad-permuted K)
// Block = 256 threads = 4 nodes x 64 float4 lanes; grid = (N/4, 4)
// ---------------------------------------------------------------------------
__global__ void __launch_bounds__(256) gather_mean_kernel(
    const int*   __restrict__ nodes,
    const int*   __restrict__ neigh_idx,
    const float* __restrict__ table_self,
    const float* __restrict__ tables_to)
{
    const int c   = blockIdx.y;
    const int sub = threadIdx.x >> 6;
    const int d4  = threadIdx.x & 63;
    const int n   = blockIdx.x * 4 + sub;
    // this thread's 4 floats are k = 4*d4 .. 4*d4+3 -> permuted positions
    // base + {0,4,8,12} with base = 16*(d4>>2) + (d4&3)
    const int pbase = ((d4 >> 2) << 4) + (d4 & 3);

    if (c == 3) {
        int i = __ldg(nodes + n);
        float4 v = reinterpret_cast<const float4*>(table_self + (size_t)i * DD)[d4];
        float* dst = g_X + (size_t)n * KDIM + 3 * DD + pbase;
        dst[0] = to_tf32(v.x); dst[4] = to_tf32(v.y);
        dst[8] = to_tf32(v.z); dst[12] = to_tf32(v.w);
        return;
    }

    __shared__ int s_idx[4][KK];
    if (threadIdx.x < 4 * KK) {
        int nn = blockIdx.x * 4 + threadIdx.x / KK;
        int kk = threadIdx.x % KK;
        s_idx[threadIdx.x / KK][kk] = neigh_idx[((size_t)c * NN + nn) * KK + kk];
    }
    __syncthreads();

    const float* tbl = tables_to + (size_t)c * NTOT * DD;
    float4 acc = make_float4(0.f, 0.f, 0.f, 0.f);
#pragma unroll
    for (int k = 0; k < KK; ++k) {
        int i = s_idx[sub][k];
        float4 v = reinterpret_cast<const float4*>(tbl + (size_t)i * DD)[d4];
        acc.x += v.x; acc.y += v.y; acc.z += v.z; acc.w += v.w;
    }
    const float s = 1.f / (float)KK;
    float* dst = g_X + (size_t)n * KDIM + (size_t)c * DD + pbase;
    dst[0]  = to_tf32(acc.x * s); dst[4]  = to_tf32(acc.y * s);
    dst[8]  = to_tf32(acc.z * s); dst[12] = to_tf32(acc.w * s);
}

// ---------------------------------------------------------------------------
// K3: H = relu(X @ M^T); out = bag-mean(H, 8)
// TF32 mma m16n8k8.  CTA 128x128, 128 threads (4 warps, 2m x 2n, warp tile
// 64x64 -> 2x smem-read redundancy instead of 3x), BK=32, 2-stage cp.async.
// Smem rows are 48 floats (192B): adjacent rows shift banks by 16, making
// every warp-wide LDS.128 fragment load conflict-free.
// ---------------------------------------------------------------------------
#define GBM 128
#define GBN 128
#define GBK 32
#define SROW 48                          // floats per 32-K row (192 B)
#define STAGE_F (GBM * SROW)             // 6144 floats per matrix
#define STAGE_TOT (2 * STAGE_F)          // A+B per stage
#define NKC (KDIM / GBK)                 // 32
#define CLD 132                          // epilogue Cs stride (128+4)
#define G_SMEM_BYTES (2 * STAGE_TOT * 4) // 98304 B

__global__ void __launch_bounds__(128, 2) gemm_relu_bag_kernel(float* __restrict__ out)
{
    extern __shared__ float smem[];

    const int tid  = threadIdx.x;
    const int lane = tid & 31;
    const int wid  = tid >> 5;           // 0..3
    const int wm   = wid & 1;            // rows wm*64
    const int wn   = wid >> 1;           // cols wn*64
    const int g    = lane >> 2;          // 0..7
    const int t    = lane & 3;           // 0..3

    const float* Abase = g_X + (size_t)blockIdx.x * GBM * KDIM;
    const float* Bbase = g_M + (size_t)blockIdx.y * GBN * KDIM;

    float acc[4][8][4];
#pragma unroll
    for (int i = 0; i < 4; ++i)
#pragma unroll
        for (int j = 0; j < 8; ++j)
#pragma unroll
            for (int r = 0; r < 4; ++r) acc[i][j][r] = 0.f;

    // fill one stage: A 128x32 + B 128x32 floats, 16B chunks, 16/thread
#define FILL_STAGE(slot, kc)                                                   \
    {                                                                          \
        float* sA_ = smem + (slot) * STAGE_TOT;                                \
        float* sB_ = sA_ + STAGE_F;                                            \
        const int ko_ = (kc) * GBK;                                            \
        _Pragma("unroll")                                                      \
        for (int i_ = 0; i_ < 8; ++i_) {                                       \
            int f4_ = tid + i_ * 128;                                          \
            int r_  = f4_ >> 3;                                                \
            int c_  = f4_ & 7;                                                 \
            cp_async16(sA_ + r_ * SROW + c_ * 4,                               \
                       Abase + (size_t)r_ * KDIM + ko_ + c_ * 4);              \
            cp_async16(sB_ + r_ * SROW + c_ * 4,                               \
                       Bbase + (size_t)r_ * KDIM + ko_ + c_ * 4);              \
        }                                                                      \
        asm volatile("cp.async.commit_group;");                                \
    }

    FILL_STAGE(0, 0)

    for (int kc = 0; kc < NKC; ++kc) {
        if (kc + 1 < NKC) {
            FILL_STAGE((kc + 1) & 1, kc + 1)
            asm volatile("cp.async.wait_group 1;" ::: "memory");
        } else {
            asm volatile("cp.async.wait_group 0;" ::: "memory");
        }
        __syncthreads();

        const float* As = smem + (kc & 1) * STAGE_TOT;
        const float* Bs = As + STAGE_F;

#pragma unroll
        for (int kk = 0; kk < 2; ++kk) {          // two 16-K groups per stage
            const int coff = kk * 16 + t * 4;
            float4 a0[4], a1[4];
#pragma unroll
            for (int mi = 0; mi < 4; ++mi) {
                int r0 = wm * 64 + mi * 16 + g;
                a0[mi] = *reinterpret_cast<const float4*>(As + r0 * SROW + coff);
                a1[mi] = *reinterpret_cast<const float4*>(As + (r0 + 8) * SROW + coff);
            }
#pragma unroll
            for (int nj = 0; nj < 8; ++nj) {
                int cn = wn * 64 + nj * 8 + g;
                float4 b = *reinterpret_cast<const float4*>(Bs + cn * SROW + coff);
#pragma unroll
                for (int mi = 0; mi < 4; ++mi) {
                    asm volatile(
                        "mma.sync.aligned.m16n8k8.row.col.f32.tf32.tf32.f32 "
                        "{%0,%1,%2,%3}, {%4,%5,%6,%7}, {%8,%9}, {%0,%1,%2,%3};"
                        : "+f"(acc[mi][nj][0]), "+f"(acc[mi][nj][1]),
                          "+f"(acc[mi][nj][2]), "+f"(acc[mi][nj][3])
                        : "r"(__float_as_uint(a0[mi].x)),
                          "r"(__float_as_uint(a1[mi].x)),
                          "r"(__float_as_uint(a0[mi].y)),
                          "r"(__float_as_uint(a1[mi].y)),
                          "r"(__float_as_uint(b.x)), "r"(__float_as_uint(b.y)));
                    asm volatile(
                        "mma.sync.aligned.m16n8k8.row.col.f32.tf32.tf32.f32 "
                        "{%0,%1,%2,%3}, {%4,%5,%6,%7}, {%8,%9}, {%0,%1,%2,%3};"
                        : "+f"(acc[mi][nj][0]), "+f"(acc[mi][nj][1]),
                          "+f"(acc[mi][nj][2]), "+f"(acc[mi][nj][3])
                        : "r"(__float_as_uint(a0[mi].z)),
                          "r"(__float_as_uint(a1[mi].z)),
                          "r"(__float_as_uint(a0[mi].w)),
                          "r"(__float_as_uint(a1[mi].w)),
                          "r"(__float_as_uint(b.z)), "r"(__float_as_uint(b.w)));
                }
            }
        }
        __syncthreads();
    }
#undef FILL_STAGE

    // ---- epilogue: relu -> Cs[128][132] -> bag-mean(8) -> out ----
    float* Cs = smem;
#pragma unroll
    for (int mi = 0; mi < 4; ++mi) {
#pragma unroll
        for (int nj = 0; nj < 8; ++nj) {
            int r0 = wm * 64 + mi * 16 + g;
            int c0 = wn * 64 + nj * 8 + 2 * t;
            Cs[r0 * CLD + c0]           = fmaxf(acc[mi][nj][0], 0.f);
            Cs[r0 * CLD + c0 + 1]       = fmaxf(acc[mi][nj][1], 0.f);
            Cs[(r0 + 8) * CLD + c0]     = fmaxf(acc[mi][nj][2], 0.f);
            Cs[(r0 + 8) * CLD + c0 + 1] = fmaxf(acc[mi][nj][3], 0.f);
        }
    }
    __syncthreads();

    const int col = tid;                          // 0..127
#pragma unroll
    for (int gg = 0; gg < GBM / BAG; ++gg) {
        float s = 0.f;
#pragma unroll
        for (int r = 0; r < BAG; ++r) s += Cs[(gg * BAG + r) * CLD + col];
        out[(size_t)(blockIdx.x * (GBM / BAG) + gg) * OUTD + blockIdx.y * GBN + col]
            = s * (1.f / BAG);
    }
}

// ---------------------------------------------------------------------------
extern "C" void kernel_launch(void* const* d_in, const int* in_sizes, int n_in,
                              void* d_out, int out_size)
{
    (void)in_sizes; (void)n_in; (void)out_size;
    const int*   nodes      = (const int*)  d_in[0];
    const int*   neigh_idx  = (const int*)  d_in[1];
    const float* table_self = (const float*)d_in[2];
    const float* tables_to  = (const float*)d_in[3];
    const float* W_self     = (const float*)d_in[4];
    const float* W_rel      = (const float*)d_in[5];
    const float* W_comp     = (const float*)d_in[6];
    float*       out        = (float*)d_out;

    cudaFuncSetAttribute(gemm_relu_bag_kernel,
                         cudaFuncAttributeMaxDynamicSharedMemorySize,
                         G_SMEM_BYTES);

    fuse_weights_kernel<<<512, 256>>>(W_self, W_rel, W_comp);
    gather_mean_kernel<<<dim3(NN / 4, 4), 256>>>(nodes, neigh_idx, table_self, tables_to);
    gemm_relu_bag_kernel<<<dim3(NN / GBM, OUTD / GBN), 128, G_SMEM_BYTES>>>(out);
}

// round 9
// speedup vs baseline: 1.6250x; 1.2719x over previous
#include <cuda_runtime.h>
#include <cuda_fp16.h>
#include <cstdint>

// Problem constants
#define NN    16384
#define KK    25
#define DD    256
#define OUTD  256
#define NTOT  100000
#define BAG   8
#define KDIM  1024

// g_X / g_M hold fp16 (same 11-bit mantissa as tf32 -> same error class,
// 2x MMA rate, half the bytes). K-dim is pair-permuted within each 16-half
// block: pair p (halves 2p,2p+1) -> slot [p0,p4,p1,p5,p2,p6,p3,p7], so one
// LDS.64 at byte offset t*8 yields halves {2t,2t+1,2t+8,2t+9}: exactly one
// m16n8k16 A/B fragment K-group. Applied to BOTH operands -> dot products
// unchanged.

__device__ __half g_M[OUTD * KDIM];          // fused weights (512 KB)
__device__ __half g_X[(size_t)NN * KDIM];    // gathered features (32 MB)

__device__ __forceinline__ void cp_async16(void* smem, const void* gmem) {
    uint32_t s = (uint32_t)__cvta_generic_to_shared(smem);
    asm volatile("cp.async.cg.shared.global [%0], [%1], 16;" :: "r"(s), "l"(gmem));
}

// ---------------------------------------------------------------------------
// K1: fuse weights.  M_c = W_comp[:, c*256:(c+1)*256] @ (W_rel[c] | W_self)
// 2 o-rows per block -> 512 blocks.  Runs on a side stream, hidden under K2.
// ---------------------------------------------------------------------------
__global__ void __launch_bounds__(256) fuse_weights_kernel(
    const float* __restrict__ W_self,
    const float* __restrict__ W_rel,
    const float* __restrict__ W_comp)
{
    const int c  = blockIdx.x >> 7;
    const int o0 = (blockIdx.x & 127) * 2;

    __shared__ float2 s_w[DD];
    {
        int j = threadIdx.x;
        s_w[j] = make_float2(W_comp[(size_t)o0 * KDIM + c * DD + j],
                             W_comp[(size_t)(o0 + 1) * KDIM + c * DD + j]);
    }
    __syncthreads();

    const float* Wsrc = (c < 3) ? (W_rel + (size_t)c * OUTD * DD) : W_self;
    const int d = threadIdx.x;

    float acc0 = 0.f, acc1 = 0.f;
#pragma unroll 8
    for (int j = 0; j < DD; ++j) {
        float v = __ldg(Wsrc + (size_t)j * DD + d);
        float2 w = s_w[j];
        acc0 += w.x * v;
        acc1 += w.y * v;
    }
    // permuted half index
    const int h = d & 15, p = h >> 1, i = h & 1;
    const int slot = ((p & 3) << 1) | ((p >> 2) & 1);
    const int pd = (d & ~15) + (slot << 1) + i;
    g_M[(size_t)o0 * KDIM + c * DD + pd]       = __float2half_rn(acc0);
    g_M[(size_t)(o0 + 1) * KDIM + c * DD + pd] = __float2half_rn(acc1);
}

// ---------------------------------------------------------------------------
// K2: gather + mean -> g_X (fp16, pair-permuted K)
// Block = 256 threads = 4 nodes x 64 float4 lanes; grid = (N/4, 4)
// Thread d4 holds k = 4*d4..4*d4+3 = pairs (2*(d4&3), +1) of block d4>>2:
// slots s0 = [0,4,1,5][d4&3] and s0+2  ->  two half2 stores.
// ---------------------------------------------------------------------------
__global__ void __launch_bounds__(256) gather_mean_kernel(
    const int*   __restrict__ nodes,
    const int*   __restrict__ neigh_idx,
    const float* __restrict__ table_self,
    const float* __restrict__ tables_to)
{
    const int c   = blockIdx.y;
    const int sub = threadIdx.x >> 6;
    const int d4  = threadIdx.x & 63;
    const int n   = blockIdx.x * 4 + sub;
    const int s0  = ((d4 & 1) << 2) | ((d4 >> 1) & 1);   // [0,4,1,5][d4&3]

    if (c == 3) {
        int i = __ldg(nodes + n);
        float4 v = reinterpret_cast<const float4*>(table_self + (size_t)i * DD)[d4];
        __half* dst = g_X + (size_t)n * KDIM + 3 * DD + ((d4 >> 2) << 4);
        *reinterpret_cast<__half2*>(dst + s0 * 2)       = __floats2half2_rn(v.x, v.y);
        *reinterpret_cast<__half2*>(dst + (s0 + 2) * 2) = __floats2half2_rn(v.z, v.w);
        return;
    }

    __shared__ int s_idx[4][KK];
    if (threadIdx.x < 4 * KK) {
        int nn = blockIdx.x * 4 + threadIdx.x / KK;
        int kk = threadIdx.x % KK;
        s_idx[threadIdx.x / KK][kk] = neigh_idx[((size_t)c * NN + nn) * KK + kk];
    }
    __syncthreads();

    const float* tbl = tables_to + (size_t)c * NTOT * DD;
    float4 acc = make_float4(0.f, 0.f, 0.f, 0.f);
#pragma unroll
    for (int k = 0; k < KK; ++k) {
        int i = s_idx[sub][k];
        float4 v = reinterpret_cast<const float4*>(tbl + (size_t)i * DD)[d4];
        acc.x += v.x; acc.y += v.y; acc.z += v.z; acc.w += v.w;
    }
    const float s = 1.f / (float)KK;
    __half* dst = g_X + (size_t)n * KDIM + (size_t)c * DD + ((d4 >> 2) << 4);
    *reinterpret_cast<__half2*>(dst + s0 * 2)       = __floats2half2_rn(acc.x * s, acc.y * s);
    *reinterpret_cast<__half2*>(dst + (s0 + 2) * 2) = __floats2half2_rn(acc.z * s, acc.w * s);
}

// ---------------------------------------------------------------------------
// K3: H = relu(X @ M^T); out = bag-mean(H, 8)
// FP16 mma m16n8k16.  CTA 128x128, 128 threads (4 warps, 2m x 2n, warp tile
// 64x64), BK=32 halves (64B rows), 2-stage cp.async.
// Smem row stride 96B: addresses {g*96 + t*8} tile mod 128 perfectly ->
// conflict-free LDS.64 fragment loads in both 16-lane phases.
// ---------------------------------------------------------------------------
#define GBM 128
#define GBN 128
#define BKH 32                            // halves per panel row
#define SROWH 48                          // halves per smem row (96 B)
#define STAGE_H (GBM * SROWH)             // halves per matrix per stage (6144)
#define STAGE_TOT (2 * STAGE_H)
#define NKC (KDIM / BKH)                  // 32 panels
#define CLD 132                           // epilogue Cs stride
#define G_SMEM_BYTES (GBM * CLD * 4)      // 67584 (>= 2*STAGE_TOT*2 = 49152)

__global__ void __launch_bounds__(128, 2) gemm_relu_bag_kernel(float* __restrict__ out)
{
    extern __shared__ __align__(16) char dynsm[];
    __half* smemh = reinterpret_cast<__half*>(dynsm);

    const int tid  = threadIdx.x;
    const int lane = tid & 31;
    const int wid  = tid >> 5;           // 0..3
    const int wm   = wid & 1;            // rows wm*64
    const int wn   = wid >> 1;           // cols wn*64
    const int g    = lane >> 2;          // 0..7
    const int t    = lane & 3;           // 0..3

    const __half* Abase = g_X + (size_t)blockIdx.x * GBM * KDIM;
    const __half* Bbase = g_M + (size_t)blockIdx.y * GBN * KDIM;

    float acc[4][8][4];
#pragma unroll
    for (int i = 0; i < 4; ++i)
#pragma unroll
        for (int j = 0; j < 8; ++j)
#pragma unroll
            for (int r = 0; r < 4; ++r) acc[i][j][r] = 0.f;

    // fill one stage: A 128x64B + B 128x64B, 16B chunks, 8 per thread
#define FILL_STAGE(slot, kc)                                                   \
    {                                                                          \
        __half* sA_ = smemh + (slot) * STAGE_TOT;                              \
        __half* sB_ = sA_ + STAGE_H;                                           \
        const int ko_ = (kc) * BKH;                                            \
        _Pragma("unroll")                                                      \
        for (int i_ = 0; i_ < 4; ++i_) {                                       \
            int f_ = tid + i_ * 128;                                           \
            int r_ = f_ >> 2;                                                  \
            int c_ = f_ & 3;                                                   \
            cp_async16(sA_ + r_ * SROWH + c_ * 8,                              \
                       Abase + (size_t)r_ * KDIM + ko_ + c_ * 8);              \
            cp_async16(sB_ + r_ * SROWH + c_ * 8,                              \
                       Bbase + (size_t)r_ * KDIM + ko_ + c_ * 8);              \
        }                                                                      \
        asm volatile("cp.async.commit_group;");                                \
    }

    FILL_STAGE(0, 0)

    for (int kc = 0; kc < NKC; ++kc) {
        if (kc + 1 < NKC) {
            FILL_STAGE((kc + 1) & 1, kc + 1)
            asm volatile("cp.async.wait_group 1;" ::: "memory");
        } else {
            asm volatile("cp.async.wait_group 0;" ::: "memory");
        }
        __syncthreads();

        const __half* As = smemh + (kc & 1) * STAGE_TOT;
        const __half* Bs = As + STAGE_H;

#pragma unroll
        for (int kk = 0; kk < 2; ++kk) {          // two K16 groups per panel
            const int coff = kk * 16 + t * 4;     // halves
            uint2 alo[4], ahi[4];
#pragma unroll
            for (int mi = 0; mi < 4; ++mi) {
                int r0 = wm * 64 + mi * 16 + g;
                alo[mi] = *reinterpret_cast<const uint2*>(As + r0 * SROWH + coff);
                ahi[mi] = *reinterpret_cast<const uint2*>(As + (r0 + 8) * SROWH + coff);
            }
#pragma unroll
            for (int nj = 0; nj < 8; ++nj) {
                int cn = wn * 64 + nj * 8 + g;
                uint2 b = *reinterpret_cast<const uint2*>(Bs + cn * SROWH + coff);
#pragma unroll
                for (int mi = 0; mi < 4; ++mi) {
                    asm volatile(
                        "mma.sync.aligned.m16n8k16.row.col.f32.f16.f16.f32 "
                        "{%0,%1,%2,%3}, {%4,%5,%6,%7}, {%8,%9}, {%0,%1,%2,%3};"
                        : "+f"(acc[mi][nj][0]), "+f"(acc[mi][nj][1]),
                          "+f"(acc[mi][nj][2]), "+f"(acc[mi][nj][3])
                        : "r"(alo[mi].x), "r"(ahi[mi].x),
                          "r"(alo[mi].y), "r"(ahi[mi].y),
                          "r"(b.x), "r"(b.y));
                }
            }
        }
        __syncthreads();
    }
#undef FILL_STAGE

    // ---- epilogue: relu -> Cs[128][132] -> bag-mean(8) -> out ----
    float* Cs = reinterpret_cast<float*>(dynsm);
#pragma unroll
    for (int mi = 0; mi < 4; ++mi) {
#pragma unroll
        for (int nj = 0; nj < 8; ++nj) {
            int r0 = wm * 64 + mi * 16 + g;
            int c0 = wn * 64 + nj * 8 + 2 * t;
            Cs[r0 * CLD + c0]           = fmaxf(acc[mi][nj][0], 0.f);
            Cs[r0 * CLD + c0 + 1]       = fmaxf(acc[mi][nj][1], 0.f);
            Cs[(r0 + 8) * CLD + c0]     = fmaxf(acc[mi][nj][2], 0.f);
            Cs[(r0 + 8) * CLD + c0 + 1] = fmaxf(acc[mi][nj][3], 0.f);
        }
    }
    __syncthreads();

    const int col = tid;                          // 0..127
#pragma unroll
    for (int gg = 0; gg < GBM / BAG; ++gg) {
        float s = 0.f;
#pragma unroll
        for (int r = 0; r < BAG; ++r) s += Cs[(gg * BAG + r) * CLD + col];
        out[(size_t)(blockIdx.x * (GBM / BAG) + gg) * OUTD + blockIdx.y * GBN + col]
            = s * (1.f / BAG);
    }
}

// ---------------------------------------------------------------------------
// side stream + events for forked capture (host objects only; created once
// at static-init time, used identically on every call -> deterministic)
// ---------------------------------------------------------------------------
namespace {
struct HxSide {
    cudaStream_t side;
    cudaEvent_t  evFork, evJoin;
    HxSide() {
        cudaStreamCreateWithFlags(&side, cudaStreamNonBlocking);
        cudaEventCreateWithFlags(&evFork, cudaEventDisableTiming);
        cudaEventCreateWithFlags(&evJoin, cudaEventDisableTiming);
    }
};
HxSide hx;
}

extern "C" void kernel_launch(void* const* d_in, const int* in_sizes, int n_in,
                              void* d_out, int out_size)
{
    (void)in_sizes; (void)n_in; (void)out_size;
    const int*   nodes      = (const int*)  d_in[0];
    const int*   neigh_idx  = (const int*)  d_in[1];
    const float* table_self = (const float*)d_in[2];
    const float* tables_to  = (const float*)d_in[3];
    const float* W_self     = (const float*)d_in[4];
    const float* W_rel      = (const float*)d_in[5];
    const float* W_comp     = (const float*)d_in[6];
    float*       out        = (float*)d_out;

    cudaFuncSetAttribute(gemm_relu_bag_kernel,
                         cudaFuncAttributeMaxDynamicSharedMemorySize,
                         G_SMEM_BYTES);

    // fork: fuse runs on the side stream concurrently with gather
    cudaEventRecord(hx.evFork, 0);
    cudaStreamWaitEvent(hx.side, hx.evFork, 0);
    fuse_weights_kernel<<<512, 256, 0, hx.side>>>(W_self, W_rel, W_comp);
    cudaEventRecord(hx.evJoin, hx.side);

    gather_mean_kernel<<<dim3(NN / 4, 4), 256>>>(nodes, neigh_idx, table_self, tables_to);

    // join before the GEMM consumes g_M
    cudaStreamWaitEvent(0, hx.evJoin, 0);
    gemm_relu_bag_kernel<<<dim3(NN / GBM, OUTD / GBN), 128, G_SMEM_BYTES>>>(out);
}